// round 17
// baseline (speedup 1.0000x reference)
#include <cuda_runtime.h>

// Capsule dynamic routing. B=64, N=4096, I=8, C=32, D=16, 3 routing iters.
// NO separate weight prepass: caps_pass0 stages RAW W rows (cp.async, padded
//   33-f4 smem rows), builds j-pair f32x2 operands in registers, computes the
//   uniform-coupling pass AND writes g_Wil (interleaved W) for caps_pass12.
// caps_pass0: 8 b/thread, 64 b/CTA; 148 CTAs x 26/28 n; triple-buffered.
// caps_pass12 (measured-best, unchanged): 4 b/thread, 32 b/CTA; grid (74,2)
//   x 54/56 n; o in regs; hat/logit/acc fma.rn.f32x2; softmax 5-shfl (lane=c);
//   triple-buffered cp.async from g_Wil.
// caps_reduce: 256 CTAs, 8-way uneven chunk split + shfl merge + squash.

#define B_ 64
#define N_ 4096
#define C_ 32

using u64 = unsigned long long;

__device__ float4 g_Wil[(size_t)N_ * 1024];              // 64MB interleaved W
__device__ float g_part[(size_t)148 * B_ * C_ * 16];     // 19.4MB partials
__device__ float g_Ocum[B_ * C_ * 16];                   // cumulative outs

__device__ __forceinline__ u64 fma2(u64 a, u64 b, u64 c) {
    u64 d; asm("fma.rn.f32x2 %0,%1,%2,%3;" : "=l"(d) : "l"(a), "l"(b), "l"(c)); return d;
}
__device__ __forceinline__ u64 mul2(u64 a, u64 b) {
    u64 d; asm("mul.rn.f32x2 %0,%1,%2;" : "=l"(d) : "l"(a), "l"(b)); return d;
}
__device__ __forceinline__ u64 pack2(float x) {
    u64 d; asm("mov.b64 %0,{%1,%1};" : "=l"(d) : "f"(x)); return d;
}
__device__ __forceinline__ u64 pack2f(float lo, float hi) {
    u64 d; asm("mov.b64 %0,{%1,%2};" : "=l"(d) : "f"(lo), "f"(hi)); return d;
}
__device__ __forceinline__ float hadd2(u64 v) {
    float a, b; asm("mov.b64 {%0,%1},%2;" : "=f"(a), "=f"(b) : "l"(v)); return a + b;
}
__device__ __forceinline__ float2 unpk(u64 v) {
    float a, b; asm("mov.b64 {%0,%1},%2;" : "=f"(a), "=f"(b) : "l"(v)); return make_float2(a, b);
}
__device__ __forceinline__ unsigned smem_u32(const void* p) {
    unsigned a; asm("{ .reg .u64 t; cvta.to.shared.u64 t, %1; cvt.u32.u64 %0, t; }" : "=r"(a) : "l"(p));
    return a;
}
__device__ __forceinline__ void cpa16(unsigned dst, const void* src) {
    asm volatile("cp.async.cg.shared.global [%0], [%1], 16;" :: "r"(dst), "l"(src));
}
__device__ __forceinline__ void cpa_commit() { asm volatile("cp.async.commit_group;"); }
__device__ __forceinline__ void cpa_wait2() { asm volatile("cp.async.wait_group 2;"); }
__device__ __forceinline__ void cpa_wait1() { asm volatile("cp.async.wait_group 1;"); }
__device__ __forceinline__ void cpa_wait0() { asm volatile("cp.async.wait_group 0;"); }

// ---------------- pass 0: uniform coupling + g_Wil producer, 148 CTAs ----------------
// smem: raw W 3 bufs x 2 n x 32 rows x 33 f4 = 101376 B, then
//       sXp [bl 64][n<=28 stride 224][i] = 114688 B. Total 216064 B.
__global__ void __launch_bounds__(256, 1)
caps_pass0(const float* __restrict__ X, const float* __restrict__ Wg) {
    extern __shared__ char smraw[];
    float4* raw = reinterpret_cast<float4*>(smraw);              // 6336 f4
    u64* sXp = reinterpret_cast<u64*>(smraw + 101376);
    const int chunk = blockIdx.x;
    const int count = 13 + (chunk < 124 ? 1 : 0);                // 2n-units
    const int n0 = (chunk * 13 + min(chunk, 124)) * 2;
    const int tid = threadIdx.x, c = tid & 31, w = tid >> 5;
    const unsigned rawA = smem_u32(raw);

    // stage X as duplicated pairs (guarded: rem < 4*count f4 per bl)
    const int remMax = 4 * count;                                // <= 56
    for (int t = tid; t < 64 * 64; t += 256) {
        int bl = t >> 6, rem = t & 63;                           // rem = n*2+ih
        if (rem < remMax) {
            float4 v = reinterpret_cast<const float4*>(X)[(size_t)bl * 8192 + n0 * 2 + rem];
            u64* d = sXp + bl * 224 + (rem >> 1) * 8 + (rem & 1) * 4;
            d[0] = pack2(v.x); d[1] = pack2(v.y); d[2] = pack2(v.z); d[3] = pack2(v.w);
        }
    }

    u64 acc[8][8];
    #pragma unroll
    for (int bi = 0; bi < 8; ++bi)
        #pragma unroll
        for (int q = 0; q < 8; ++q) acc[bi][q] = 0ull;

    // raw W staging: 2 n per sub. thread -> row = tid>>2 (ln*32+c), part = tid&3.
    const int s_row = tid >> 2, s_part = tid & 3;
    const int s_ln = s_row >> 5, s_c = s_row & 31;
    auto stage = [&](int sub) {
        const int n = n0 + sub * 2 + s_ln;
        const float4* src = reinterpret_cast<const float4*>(Wg)
                              + ((size_t)s_c * N_ + n) * 32 + s_part * 8;
        unsigned dst = rawA + (unsigned)(((sub % 3) * 2 + s_ln) * 1056
                                          + s_c * 33 + s_part * 8) * 16;
        #pragma unroll
        for (int k = 0; k < 8; ++k) cpa16(dst + k * 16, src + k);
        cpa_commit();
    };
    stage(0);
    if (count > 1) stage(1);

    for (int sub = 0; sub < count; ++sub) {
        if (sub + 2 < count) { stage(sub + 2); cpa_wait2(); }
        else if (sub + 1 < count) cpa_wait1();
        else cpa_wait0();
        __syncthreads();
        #pragma unroll
        for (int ln = 0; ln < 2; ++ln) {
            const float4* row = raw + ((sub % 3) * 2 + ln) * 1056 + c * 33;
            const int nloc = sub * 2 + ln;
            const int n = n0 + nloc;
            #pragma unroll
            for (int q = 0; q < 4; ++q) {
                float4 J0 = row[8 * q + 0], J1 = row[8 * q + 1];   // j=4q   i0-3, i4-7
                float4 J2 = row[8 * q + 2], J3 = row[8 * q + 3];   // j=4q+1
                float4 J4 = row[8 * q + 4], J5 = row[8 * q + 5];   // j=4q+2
                float4 J6 = row[8 * q + 6], J7 = row[8 * q + 7];   // j=4q+3
                u64 wlo[8], whi[8];
                wlo[0] = pack2f(J0.x, J2.x); whi[0] = pack2f(J0.y, J2.y);
                wlo[1] = pack2f(J0.z, J2.z); whi[1] = pack2f(J0.w, J2.w);
                wlo[2] = pack2f(J1.x, J3.x); whi[2] = pack2f(J1.y, J3.y);
                wlo[3] = pack2f(J1.z, J3.z); whi[3] = pack2f(J1.w, J3.w);
                wlo[4] = pack2f(J4.x, J6.x); whi[4] = pack2f(J4.y, J6.y);
                wlo[5] = pack2f(J4.z, J6.z); whi[5] = pack2f(J4.w, J6.w);
                wlo[6] = pack2f(J5.x, J7.x); whi[6] = pack2f(J5.y, J7.y);
                wlo[7] = pack2f(J5.z, J7.z); whi[7] = pack2f(J5.w, J7.w);
                if (w == q) {                    // warps 0-3 emit g_Wil slice q
                    #pragma unroll
                    for (int k = 0; k < 8; ++k) {
                        ulonglong2 vv; vv.x = wlo[k]; vv.y = whi[k];
                        reinterpret_cast<ulonglong2*>(
                            g_Wil + (size_t)n * 1024 + (q * 8 + k) * 32 + c)[0] = vv;
                    }
                }
                #pragma unroll
                for (int bi = 0; bi < 8; ++bi) {
                    const ulonglong2* xp = reinterpret_cast<const ulonglong2*>(
                        sXp + (w * 8 + bi) * 224 + nloc * 8);
                    ulonglong2 xA = xp[0], xB = xp[1], xC = xp[2], xD = xp[3];
                    u64 a0 = acc[bi][2 * q], a1 = acc[bi][2 * q + 1];
                    a0 = fma2(xA.x, wlo[0], a0); a0 = fma2(xA.y, whi[0], a0);
                    a0 = fma2(xB.x, wlo[1], a0); a0 = fma2(xB.y, whi[1], a0);
                    a0 = fma2(xC.x, wlo[2], a0); a0 = fma2(xC.y, whi[2], a0);
                    a0 = fma2(xD.x, wlo[3], a0); a0 = fma2(xD.y, whi[3], a0);
                    a1 = fma2(xA.x, wlo[4], a1); a1 = fma2(xA.y, whi[4], a1);
                    a1 = fma2(xB.x, wlo[5], a1); a1 = fma2(xB.y, whi[5], a1);
                    a1 = fma2(xC.x, wlo[6], a1); a1 = fma2(xC.y, whi[6], a1);
                    a1 = fma2(xD.x, wlo[7], a1); a1 = fma2(xD.y, whi[7], a1);
                    acc[bi][2 * q] = a0; acc[bi][2 * q + 1] = a1;
                }
            }
        }
        __syncthreads();
    }

    #pragma unroll
    for (int bi = 0; bi < 8; ++bi) {
        const int b = w * 8 + bi;
        float4* dst = reinterpret_cast<float4*>(g_part) + (((size_t)chunk * B_ + b) * C_ + c) * 4;
        #pragma unroll
        for (int qd = 0; qd < 4; ++qd) {
            float2 p0 = unpk(acc[bi][2 * qd]), p1 = unpk(acc[bi][2 * qd + 1]);
            dst[qd] = make_float4(p0.x * (1.f / 32.f), p0.y * (1.f / 32.f),
                                  p1.x * (1.f / 32.f), p1.y * (1.f / 32.f));
        }
    }
}

// ---------------- pass 1/2: 4 b/thread, o in regs, grid (74, 2) (UNCHANGED) ----------------
// smem: sW 96KB (3 buf x 2 n) + sXp 112KB ([bl 32][n<=56 stride 448][i]) = 208KB.
__global__ void __launch_bounds__(256, 1)
caps_pass12(const float* __restrict__ X) {
    extern __shared__ char smraw[];
    float4* sW = reinterpret_cast<float4*>(smraw);
    u64* sXp = reinterpret_cast<u64*>(smraw + 98304);
    const int chunk = blockIdx.x, half = blockIdx.y;
    const int count = 27 + (chunk < 50 ? 1 : 0);                 // 2n-units
    const int n0 = (chunk * 27 + min(chunk, 50)) * 2;
    const int b0 = half * 32;
    const int tid = threadIdx.x, c = tid & 31, w = tid >> 5;
    const unsigned sWa = smem_u32(sW);

    const int remMax = 4 * count;                                // <= 112
    for (int t = tid; t < 32 * 128; t += 256) {
        int bl = t >> 7, rem = t & 127;
        if (rem < remMax) {
            float4 v = reinterpret_cast<const float4*>(X)[(size_t)(b0 + bl) * 8192 + n0 * 2 + rem];
            u64* d = sXp + bl * 448 + (rem >> 1) * 8 + (rem & 1) * 4;
            d[0] = pack2(v.x); d[1] = pack2(v.y); d[2] = pack2(v.z); d[3] = pack2(v.w);
        }
    }

    // hoist o (cumulative outs) to registers: loop-invariant over n
    u64 o2[4][8];
    #pragma unroll
    for (int bi = 0; bi < 4; ++bi) {
        const int b = b0 + w * 4 + bi;
        const ulonglong2* op = reinterpret_cast<const ulonglong2*>(g_Ocum + (b * C_ + c) * 16);
        #pragma unroll
        for (int qd = 0; qd < 4; ++qd) {
            ulonglong2 u = op[qd];
            o2[bi][2 * qd] = u.x; o2[bi][2 * qd + 1] = u.y;
        }
    }

    u64 acc[4][8];
    #pragma unroll
    for (int bi = 0; bi < 4; ++bi)
        #pragma unroll
        for (int jp = 0; jp < 8; ++jp) acc[bi][jp] = 0ull;

    auto stage = [&](int sub) {
        const float4* src = g_Wil + (size_t)(n0 + sub * 2) * 1024;
        unsigned dst = sWa + (unsigned)((sub % 3) * 2048 + tid) * 16;
        #pragma unroll
        for (int k = 0; k < 8; ++k) cpa16(dst + k * 4096, src + tid + k * 256);
        cpa_commit();
    };
    stage(0);
    if (count > 1) stage(1);

    for (int sub = 0; sub < count; ++sub) {
        if (sub + 2 < count) { stage(sub + 2); cpa_wait2(); }
        else if (sub + 1 < count) cpa_wait1();
        else cpa_wait0();
        __syncthreads();
        const float4* Wb = sW + (sub % 3) * 2048;
        #pragma unroll
        for (int ln = 0; ln < 2; ++ln) {
            const float4* Wn = Wb + ln * 1024;
            const int nloc = sub * 2 + ln;
            u64 hat[4][8];
            #pragma unroll
            for (int q = 0; q < 4; ++q) {
                ulonglong2 Wq[8];
                #pragma unroll
                for (int k = 0; k < 8; ++k)
                    Wq[k] = reinterpret_cast<const ulonglong2*>(Wn + (q * 8 + k) * 32)[c];
                #pragma unroll
                for (int bi = 0; bi < 4; ++bi) {
                    const ulonglong2* xp = reinterpret_cast<const ulonglong2*>(
                        sXp + (w * 4 + bi) * 448 + nloc * 8);
                    ulonglong2 xA = xp[0], xB = xp[1], xC = xp[2], xD = xp[3];
                    u64 h0 = mul2(xA.x, Wq[0].x);
                    h0 = fma2(xA.y, Wq[0].y, h0);
                    h0 = fma2(xB.x, Wq[1].x, h0); h0 = fma2(xB.y, Wq[1].y, h0);
                    h0 = fma2(xC.x, Wq[2].x, h0); h0 = fma2(xC.y, Wq[2].y, h0);
                    h0 = fma2(xD.x, Wq[3].x, h0); h0 = fma2(xD.y, Wq[3].y, h0);
                    u64 h1 = mul2(xA.x, Wq[4].x);
                    h1 = fma2(xA.y, Wq[4].y, h1);
                    h1 = fma2(xB.x, Wq[5].x, h1); h1 = fma2(xB.y, Wq[5].y, h1);
                    h1 = fma2(xC.x, Wq[6].x, h1); h1 = fma2(xC.y, Wq[6].y, h1);
                    h1 = fma2(xD.x, Wq[7].x, h1); h1 = fma2(xD.y, Wq[7].y, h1);
                    hat[bi][2 * q] = h0; hat[bi][2 * q + 1] = h1;
                }
            }
            #pragma unroll
            for (int bi = 0; bi < 4; ++bi) {
                u64 lg = mul2(hat[bi][0], o2[bi][0]);
                lg = fma2(hat[bi][1], o2[bi][1], lg);
                lg = fma2(hat[bi][2], o2[bi][2], lg); lg = fma2(hat[bi][3], o2[bi][3], lg);
                lg = fma2(hat[bi][4], o2[bi][4], lg); lg = fma2(hat[bi][5], o2[bi][5], lg);
                lg = fma2(hat[bi][6], o2[bi][6], lg); lg = fma2(hat[bi][7], o2[bi][7], lg);
                const float e = __expf(hadd2(lg));   // logits O(1): no max-sub needed
                float s = e;
                s += __shfl_xor_sync(0xffffffffu, s, 1);
                s += __shfl_xor_sync(0xffffffffu, s, 2);
                s += __shfl_xor_sync(0xffffffffu, s, 4);
                s += __shfl_xor_sync(0xffffffffu, s, 8);
                s += __shfl_xor_sync(0xffffffffu, s, 16);
                const u64 cf = pack2(__fdividef(e, s));
                #pragma unroll
                for (int jp = 0; jp < 8; ++jp)
                    acc[bi][jp] = fma2(cf, hat[bi][jp], acc[bi][jp]);
            }
        }
        __syncthreads();
    }

    #pragma unroll
    for (int bi = 0; bi < 4; ++bi) {
        const int b = b0 + w * 4 + bi;
        float4* dst = reinterpret_cast<float4*>(g_part) + (((size_t)chunk * B_ + b) * C_ + c) * 4;
        #pragma unroll
        for (int qd = 0; qd < 4; ++qd) {
            float2 p0 = unpk(acc[bi][2 * qd]), p1 = unpk(acc[bi][2 * qd + 1]);
            dst[qd] = make_float4(p0.x, p0.y, p1.x, p1.y);
        }
    }
}

// ---------------- reduce + squash: grid 256 x 256, uneven 8-way split ----------------
__global__ void caps_reduce(float* __restrict__ out, int mode, int nch) {
    const int gt = blockIdx.x * 256 + threadIdx.x;
    const int idx4 = gt >> 3, eighth = gt & 7;
    const int kc = nch >> 3, rem = nch & 7;
    const int kstart = eighth * kc + min(eighth, rem);
    const int kcount = kc + (eighth < rem ? 1 : 0);
    float4 a = make_float4(0.f, 0.f, 0.f, 0.f);
    const float4* gp = reinterpret_cast<const float4*>(g_part) + idx4;
    for (int k = 0; k < kcount; ++k) {
        float4 v = gp[(size_t)(kstart + k) * 8192];
        a.x += v.x; a.y += v.y; a.z += v.z; a.w += v.w;
    }
    #pragma unroll
    for (int m = 1; m <= 4; m <<= 1) {
        a.x += __shfl_xor_sync(0xffffffffu, a.x, m);
        a.y += __shfl_xor_sync(0xffffffffu, a.y, m);
        a.z += __shfl_xor_sync(0xffffffffu, a.z, m);
        a.w += __shfl_xor_sync(0xffffffffu, a.w, m);
    }
    float sq = a.x * a.x + a.y * a.y + a.z * a.z + a.w * a.w;
    sq += __shfl_xor_sync(0xffffffffu, sq, 8);
    sq += __shfl_xor_sync(0xffffffffu, sq, 16);
    const float f = sq / ((1.f + sq) * sqrtf(sq + 1e-7f));
    float4 v = make_float4(a.x * f, a.y * f, a.z * f, a.w * f);
    if (eighth == 0) {
        float4* oc = reinterpret_cast<float4*>(g_Ocum);
        if (mode == 0) {
            oc[idx4] = v;
        } else if (mode == 1) {
            float4 o = oc[idx4];
            o.x += v.x; o.y += v.y; o.z += v.z; o.w += v.w;
            oc[idx4] = o;
        } else {
            reinterpret_cast<float4*>(out)[idx4] = v;
        }
    }
}

extern "C" void kernel_launch(void* const* d_in, const int* in_sizes, int n_in,
                              void* d_out, int out_size) {
    const float* X = (const float*)d_in[0];
    const float* W = (const float*)d_in[1];
    if (n_in >= 2 && in_sizes[0] != B_ * N_ * 8) {
        X = (const float*)d_in[1];
        W = (const float*)d_in[0];
    }
    float* out = (float*)d_out;

    const int smem0  = 101376 + 114688;  // 216064 B
    const int smem12 = 98304 + 114688;   // 212992 B
    cudaFuncSetAttribute(caps_pass0,  cudaFuncAttributeMaxDynamicSharedMemorySize, smem0);
    cudaFuncSetAttribute(caps_pass12, cudaFuncAttributeMaxDynamicSharedMemorySize, smem12);

    caps_pass0<<<148, 256, smem0>>>(X, W);        // also produces g_Wil
    caps_reduce<<<256, 256>>>(out, 0, 148);
    caps_pass12<<<dim3(74, 2), 256, smem12>>>(X);
    caps_reduce<<<256, 256>>>(out, 1, 74);
    caps_pass12<<<dim3(74, 2), 256, smem12>>>(X);
    caps_reduce<<<256, 256>>>(out, 2, 74);
}